// round 2
// baseline (speedup 1.0000x reference)
#include <cuda_runtime.h>
#include <cuda_bf16.h>
#include <mma.h>

using namespace nvcuda;

// Problem constants
#define BATCH   64
#define CIN     64
#define COUT    128
#define HIN     64
#define HO      62
#define SP      3844            // 62*62 spatial per batch image
#define NPIX    246016          // BATCH * SP
#define PT      128             // pixels per tile
#define NTILES  1922            // NPIX / PT (exact)
#define LDA     132             // padded ld for 128-wide smem tiles
#define LDWC    68              // padded ld for 64-wide conv W tiles
#define MAX_IT  350
#define TAUF    0.2f
#define OMT     0.8f
#define EPSF    1.0e-4f

// ---------------- device scratch (static: no runtime allocation) ----------------
__device__ float g_u0[BATCH * COUT * SP];   // 126 MB
__device__ float g_u [BATCH * COUT * SP];   // 126 MB
__device__ float g_Wt[9 * COUT * CIN];      // conv weights, [shift][o][c], tf32-rounded
__device__ float g_Wr[COUT * COUT];         // lateral weights, [o][c], tf32-rounded
__device__ unsigned int g_bar;
__device__ volatile int g_go;
__device__ volatile int g_conv;
__device__ volatile float g_sd[2];
__device__ volatile float g_su[2];

// ---------------- prep: transpose/round weights, reset control state ----------------
__global__ void prep_kernel(const float* __restrict__ Wff,
                            const float* __restrict__ Wrec)
{
    int i = blockIdx.x * blockDim.x + threadIdx.x;
    int stride = gridDim.x * blockDim.x;
    // g_Wt[s][o][c] = tf32( Wff[o][c][s] ),  Wff layout (o, c, kh, kw) contiguous
    for (int idx = i; idx < 9 * COUT * CIN; idx += stride) {
        int s = idx / (COUT * CIN);
        int r = idx - s * (COUT * CIN);
        int o = r >> 6;
        int c = r & 63;
        g_Wt[idx] = wmma::__float_to_tf32(Wff[(o * CIN + c) * 9 + s]);
    }
    for (int idx = i; idx < COUT * COUT; idx += stride) {
        g_Wr[idx] = wmma::__float_to_tf32(Wrec[idx]);   // W_rec[:, :, 0, 0] contiguous as (o*128+c)
    }
    if (i == 0) {
        g_bar = 0u;
        g_go = 0;
        g_conv = 0;
        g_sd[0] = 0.f; g_sd[1] = 0.f;
        g_su[0] = 0.f; g_su[1] = 0.f;
    }
}

// ---------------- conv: u0 = conv3x3(x, W_ff), VALID, via 9 shifted channel-GEMMs ----------------
// Output tile: 128 oc x 128 pixels per block. K = 9 shifts x 64 channels, tf32 WMMA.
extern "C" __global__ void __launch_bounds__(512, 1)
conv_kernel(const float* __restrict__ x)
{
    extern __shared__ float sm[];
    float* Ws = sm;                       // [128][LDWC]   conv W slice (o x c)
    float* As = Ws + COUT * LDWC;         // [64][LDA]     x slice (c x j)
    float* Cs = As + CIN * LDA;           // [128][LDA]    output accum
    int*   xb = (int*)(Cs + COUT * LDA);  // [128] x base address per column
    int*   ob = xb + PT;                  // [128] output base address per column

    int tid = threadIdx.x;
    int t = blockIdx.x;

    if (tid < PT) {
        int p = t * PT + tid;
        int b = p / SP;
        int s = p - b * SP;
        int h = s / HO;
        int w = s - h * HO;
        xb[tid] = (b * CIN) * (HIN * HIN) + h * HIN + w;
        ob[tid] = (b * COUT) * SP + s;
    }

    int warp = tid >> 5;
    int r  = warp >> 1;        // oc row-block 0..7
    int cg = (warp & 1) * 4;   // pixel col-block base (of 8)

    wmma::fragment<wmma::accumulator, 16, 16, 8, float> acc[4];
#pragma unroll
    for (int q = 0; q < 4; ++q) wmma::fill_fragment(acc[q], 0.0f);
    __syncthreads();

    for (int sft = 0; sft < 9; ++sft) {
        int kh = sft / 3;
        int kw = sft - 3 * kh;
        // load conv weight slice (pre-rounded tf32)
        for (int idx = tid; idx < COUT * CIN; idx += 512) {
            int o = idx >> 6;
            int c = idx & 63;
            Ws[o * LDWC + c] = g_Wt[sft * (COUT * CIN) + idx];
        }
        // load shifted x slice
        for (int idx = tid; idx < CIN * PT; idx += 512) {
            int c = idx >> 7;
            int j = idx & 127;
            As[c * LDA + j] = wmma::__float_to_tf32(x[xb[j] + c * (HIN * HIN) + kh * HIN + kw]);
        }
        __syncthreads();
#pragma unroll
        for (int k = 0; k < 8; ++k) {
            wmma::fragment<wmma::matrix_a, 16, 16, 8, wmma::precision::tf32, wmma::row_major> af;
            wmma::load_matrix_sync(af, Ws + (r * 16) * LDWC + k * 8, LDWC);
#pragma unroll
            for (int q = 0; q < 4; ++q) {
                wmma::fragment<wmma::matrix_b, 16, 16, 8, wmma::precision::tf32, wmma::row_major> bf;
                wmma::load_matrix_sync(bf, As + (k * 8) * LDA + (cg + q) * 16, LDA);
                wmma::mma_sync(acc[q], af, bf, acc[q]);
            }
        }
        __syncthreads();
    }
#pragma unroll
    for (int q = 0; q < 4; ++q)
        wmma::store_matrix_sync(Cs + (r * 16) * LDA + (cg + q) * 16, acc[q], LDA, wmma::mem_row_major);
    __syncthreads();

    for (int idx = tid; idx < COUT * PT; idx += 512) {
        int o = idx >> 7;
        int j = idx & 127;
        g_u0[ob[j] + o * SP] = Cs[o * LDA + j];
    }
}

// ---------------- persistent iteration kernel ----------------
// u_{k+1} = 0.8 u_k + 0.2 (u0 - Wr * relu(u_k - thr)),  a never materialized.
// One block per SM; each block owns a fixed set of pixel tiles across all iterations.
// Global convergence decided on-device via software grid barrier.
extern "C" __global__ void __launch_bounds__(512, 1)
iter_kernel(const float* __restrict__ thr_g, float* __restrict__ out)
{
    extern __shared__ float sm[];
    float* Wr  = sm;                       // [128][LDA]  lateral weights
    float* S   = Wr + COUT * LDA;          // [128][128]  staged raw u (or u0 on iter 0)
    float* AC  = S + COUT * PT;            // [128][LDA]  relu'ed A, then GEMM result C
    float* thr = AC + COUT * LDA;          // [128]
    int*   cb  = (int*)(thr + COUT);       // [128] column base address
    float* red = (float*)(cb + PT);        // [64] block reduction scratch
    int*   flg = (int*)(red + 64);

    int tid  = threadIdx.x;
    int warp = tid >> 5;
    int lane = tid & 31;
    int r  = warp >> 1;
    int cg = (warp & 1) * 4;
    int G  = gridDim.x;

    for (int idx = tid; idx < COUT * COUT; idx += 512) {
        int o = idx >> 7;
        int c = idx & 127;
        Wr[o * LDA + c] = g_Wr[idx];
    }
    if (tid < COUT) thr[tid] = thr_g[tid];
    __syncthreads();

    int it;
    for (it = 0; it < MAX_IT; ++it) {
        float ld = 0.f, lu = 0.f;
        const float* src = (it == 0) ? g_u0 : g_u;

        for (int t = blockIdx.x; t < NTILES; t += G) {
            __syncthreads();   // protect smem reuse across tiles
            if (tid < PT) {
                int p = t * PT + tid;
                int b = p / SP;
                int s = p - b * SP;
                cb[tid] = b * (COUT * SP) + s;
            }
            __syncthreads();
            // stage u (raw) and build A = tf32(relu(u - thr)); iter 0: src=u0, thr=0
            for (int idx = tid; idx < COUT * PT; idx += 512) {
                int c = idx >> 7;
                int j = idx & 127;
                float v = src[cb[j] + c * SP];
                S[idx] = v;
                float th = (it == 0) ? 0.f : thr[c];
                float a = v - th;
                a = a > 0.f ? a : 0.f;
                AC[c * LDA + j] = wmma::__float_to_tf32(a);
            }
            __syncthreads();
            // lateral GEMM: C[o][j] = sum_c Wr[o][c] * A[c][j]
            wmma::fragment<wmma::accumulator, 16, 16, 8, float> acc[4];
#pragma unroll
            for (int q = 0; q < 4; ++q) wmma::fill_fragment(acc[q], 0.0f);
#pragma unroll
            for (int k = 0; k < 16; ++k) {
                wmma::fragment<wmma::matrix_a, 16, 16, 8, wmma::precision::tf32, wmma::row_major> af;
                wmma::load_matrix_sync(af, Wr + (r * 16) * LDA + k * 8, LDA);
#pragma unroll
                for (int q = 0; q < 4; ++q) {
                    wmma::fragment<wmma::matrix_b, 16, 16, 8, wmma::precision::tf32, wmma::row_major> bf;
                    wmma::load_matrix_sync(bf, AC + (k * 8) * LDA + (cg + q) * 16, LDA);
                    wmma::mma_sync(acc[q], af, bf, acc[q]);
                }
            }
            __syncthreads();   // all warps done reading AC as A
#pragma unroll
            for (int q = 0; q < 4; ++q)
                wmma::store_matrix_sync(AC + (r * 16) * LDA + (cg + q) * 16, acc[q], LDA, wmma::mem_row_major);
            __syncthreads();
            // elementwise update + norm accumulation
            for (int idx = tid; idx < COUT * PT; idx += 512) {
                int o = idx >> 7;
                int j = idx & 127;
                float lat = AC[o * LDA + j];
                float up, u0v;
                if (it == 0) { up = 0.f;     u0v = S[idx]; }
                else         { up = S[idx]; u0v = __ldg(&g_u0[cb[j] + o * SP]); }
                float un = OMT * up + TAUF * (u0v - lat);
                g_u[cb[j] + o * SP] = un;
                float d = un - up;
                ld += d * d;
                lu += un * un;
            }
        }

        // block reduction of norm partials
#pragma unroll
        for (int off = 16; off; off >>= 1) {
            ld += __shfl_down_sync(0xffffffffu, ld, off);
            lu += __shfl_down_sync(0xffffffffu, lu, off);
        }
        if (lane == 0) { red[warp] = ld; red[32 + warp] = lu; }
        __syncthreads();

        if (tid == 0) {
            float sd = 0.f, su = 0.f;
#pragma unroll
            for (int w2 = 0; w2 < 16; ++w2) { sd += red[w2]; su += red[32 + w2]; }
            atomicAdd((float*)&g_sd[it & 1], sd);
            atomicAdd((float*)&g_su[it & 1], su);
            __threadfence();
            unsigned old = atomicAdd(&g_bar, 1u);
            if (old == (unsigned)G - 1u) {
                // last block to arrive decides convergence
                float D = g_sd[it & 1];
                float U = g_su[it & 1];
                int c2 = (sqrtf(D) < EPSF * sqrtf(U)) ? 1 : 0;
                g_sd[(it + 1) & 1] = 0.f;
                g_su[(it + 1) & 1] = 0.f;
                g_conv = c2;
                atomicExch(&g_bar, 0u);
                __threadfence();
                g_go = it + 1;
            } else {
                while (g_go < it + 1) __nanosleep(100);
            }
            __threadfence();
            *flg = g_conv;
        }
        __syncthreads();
        if (*flg) break;
        __syncthreads();
    }

    // output: a_final = relu(u - thr), same NCHW layout
    for (int t = blockIdx.x; t < NTILES; t += G) {
        __syncthreads();
        if (tid < PT) {
            int p = t * PT + tid;
            int b = p / SP;
            int s = p - b * SP;
            cb[tid] = b * (COUT * SP) + s;
        }
        __syncthreads();
        for (int idx = tid; idx < COUT * PT; idx += 512) {
            int o = idx >> 7;
            int j = idx & 127;
            float un = g_u[cb[j] + o * SP];
            float a = un - thr[o];
            out[cb[j] + o * SP] = a > 0.f ? a : 0.f;
        }
    }
}

// ---------------- launch ----------------
extern "C" void kernel_launch(void* const* d_in, const int* in_sizes, int n_in,
                              void* d_out, int out_size)
{
    const float* x    = (const float*)d_in[0];
    const float* Wff  = (const float*)d_in[1];
    const float* Wrec = (const float*)d_in[2];
    const float* thr  = (const float*)d_in[3];
    float* out = (float*)d_out;

    static int nsm = 0;
    static size_t smem_conv = 0, smem_iter = 0;
    if (nsm == 0) {
        cudaDeviceProp p;
        cudaGetDeviceProperties(&p, 0);
        nsm = p.multiProcessorCount;
        smem_conv = (size_t)(COUT * LDWC + CIN * LDA + COUT * LDA) * 4 + 2 * PT * 4;
        smem_iter = (size_t)(COUT * LDA + COUT * PT + COUT * LDA + COUT) * 4
                    + PT * 4 + 64 * 4 + 16;
        cudaFuncSetAttribute(conv_kernel, cudaFuncAttributeMaxDynamicSharedMemorySize, (int)smem_conv);
        cudaFuncSetAttribute(iter_kernel, cudaFuncAttributeMaxDynamicSharedMemorySize, (int)smem_iter);
    }

    prep_kernel<<<64, 256>>>(Wff, Wrec);
    conv_kernel<<<NTILES, 512, smem_conv>>>(x);
    iter_kernel<<<nsm, 512, smem_iter>>>(thr, out);
}

// round 3
// speedup vs baseline: 1.7606x; 1.7606x over previous
#include <cuda_runtime.h>
#include <cuda_bf16.h>
#include <mma.h>

using namespace nvcuda;

// Problem constants
#define BATCH   64
#define CIN     64
#define COUT    128
#define HIN     64
#define HO      62
#define SP      3844            // 62*62 spatial per batch image
#define NPIX    246016          // BATCH * SP
#define PT      128             // pixels per tile
#define NTILES  1922            // NPIX / PT (exact)
#define LDA     132             // padded ld for 128-wide smem tiles
#define LDWC    68              // padded ld for 64-wide conv W tiles
#define MAX_IT  352
#define TBATCH  4               // iterations per tile visit between grid syncs
#define TAUF    0.2f
#define OMT     0.8f
#define EPSF    1.0e-4f

// ---------------- device scratch (static: no runtime allocation) ----------------
__device__ float g_u0[BATCH * COUT * SP];   // 126 MB
__device__ float g_u [BATCH * COUT * SP];   // 126 MB
__device__ float g_Wt[9 * COUT * CIN];      // conv weights, [shift][o][c], tf32-rounded
__device__ float g_Wr[COUT * COUT];         // lateral weights, [o][c], tf32-rounded
__device__ unsigned int g_bar;
__device__ volatile int g_go;
__device__ volatile int g_conv;
__device__ volatile float g_sd[2];
__device__ volatile float g_su[2];

// ---------------- prep: transpose/round weights, reset control state ----------------
__global__ void prep_kernel(const float* __restrict__ Wff,
                            const float* __restrict__ Wrec)
{
    int i = blockIdx.x * blockDim.x + threadIdx.x;
    int stride = gridDim.x * blockDim.x;
    for (int idx = i; idx < 9 * COUT * CIN; idx += stride) {
        int s = idx / (COUT * CIN);
        int r = idx - s * (COUT * CIN);
        int o = r >> 6;
        int c = r & 63;
        g_Wt[idx] = wmma::__float_to_tf32(Wff[(o * CIN + c) * 9 + s]);
    }
    for (int idx = i; idx < COUT * COUT; idx += stride) {
        g_Wr[idx] = wmma::__float_to_tf32(Wrec[idx]);
    }
    if (i == 0) {
        g_bar = 0u;
        g_go = 0;
        g_conv = 0;
        g_sd[0] = 0.f; g_sd[1] = 0.f;
        g_su[0] = 0.f; g_su[1] = 0.f;
    }
}

// ---------------- conv: u0 = conv3x3(x, W_ff), VALID, via 9 shifted channel-GEMMs ----------------
extern "C" __global__ void __launch_bounds__(512, 1)
conv_kernel(const float* __restrict__ x)
{
    extern __shared__ float sm[];
    float* Ws = sm;                       // [128][LDWC]
    float* As = Ws + COUT * LDWC;         // [64][LDA]
    float* Cs = As + CIN * LDA;           // [128][LDA]
    int*   xb = (int*)(Cs + COUT * LDA);  // [128]
    int*   ob = xb + PT;                  // [128]

    int tid = threadIdx.x;
    int t = blockIdx.x;

    if (tid < PT) {
        int p = t * PT + tid;
        int b = p / SP;
        int s = p - b * SP;
        int h = s / HO;
        int w = s - h * HO;
        xb[tid] = (b * CIN) * (HIN * HIN) + h * HIN + w;
        ob[tid] = (b * COUT) * SP + s;
    }

    int warp = tid >> 5;
    int r  = warp >> 1;
    int cg = (warp & 1) * 4;

    wmma::fragment<wmma::accumulator, 16, 16, 8, float> acc[4];
#pragma unroll
    for (int q = 0; q < 4; ++q) wmma::fill_fragment(acc[q], 0.0f);
    __syncthreads();

    for (int sft = 0; sft < 9; ++sft) {
        int kh = sft / 3;
        int kw = sft - 3 * kh;
        for (int idx = tid; idx < COUT * CIN; idx += 512) {
            int o = idx >> 6;
            int c = idx & 63;
            Ws[o * LDWC + c] = g_Wt[sft * (COUT * CIN) + idx];
        }
        for (int idx = tid; idx < CIN * PT; idx += 512) {
            int c = idx >> 7;
            int j = idx & 127;
            As[c * LDA + j] = wmma::__float_to_tf32(x[xb[j] + c * (HIN * HIN) + kh * HIN + kw]);
        }
        __syncthreads();
#pragma unroll
        for (int k = 0; k < 8; ++k) {
            wmma::fragment<wmma::matrix_a, 16, 16, 8, wmma::precision::tf32, wmma::row_major> af;
            wmma::load_matrix_sync(af, Ws + (r * 16) * LDWC + k * 8, LDWC);
#pragma unroll
            for (int q = 0; q < 4; ++q) {
                wmma::fragment<wmma::matrix_b, 16, 16, 8, wmma::precision::tf32, wmma::row_major> bf;
                wmma::load_matrix_sync(bf, As + (k * 8) * LDA + (cg + q) * 16, LDA);
                wmma::mma_sync(acc[q], af, bf, acc[q]);
            }
        }
        __syncthreads();
    }
#pragma unroll
    for (int q = 0; q < 4; ++q)
        wmma::store_matrix_sync(Cs + (r * 16) * LDA + (cg + q) * 16, acc[q], LDA, wmma::mem_row_major);
    __syncthreads();

    for (int idx = tid; idx < COUT * PT; idx += 512) {
        int o = idx >> 7;
        int j = idx & 127;
        g_u0[ob[j] + o * SP] = Cs[o * LDA + j];
    }
}

// ---------------- persistent iteration kernel, TBATCH iterations per tile visit ----------------
// u_{k+1} = 0.8 u_k + 0.2 (u0 - Wr * relu(u_k - thr)).
// u and u0 stay in smem across TBATCH sub-iterations; Wr lives in register fragments.
// Global convergence checked (ratio of LAST sub-step) every TBATCH iterations via grid barrier.
extern "C" __global__ void __launch_bounds__(512, 1)
iter_kernel(const float* __restrict__ thr_g, float* __restrict__ out)
{
    extern __shared__ float sm[];
    float* U   = sm;                       // [128*128]  u tile (fp32), c-major
    float* U0  = U + COUT * PT;            // [128*128]  u0 tile (fp32)
    float* AC  = U0 + COUT * PT;           // [128][LDA] activations (tf32), then GEMM out
    float* thr = AC + COUT * LDA;          // [128]
    int*   cb  = (int*)(thr + COUT);       // [128] column base address
    float* red = (float*)(cb + PT);        // [64]
    int*   flg = (int*)(red + 64);

    int tid  = threadIdx.x;
    int warp = tid >> 5;
    int lane = tid & 31;
    int r  = warp >> 1;
    int cg = (warp & 1) * 4;
    int G  = gridDim.x;

    // stage Wr into AC, pull weight fragments into registers (tile/iteration invariant)
    for (int idx = tid; idx < COUT * COUT; idx += 512) {
        AC[(idx >> 7) * LDA + (idx & 127)] = g_Wr[idx];
    }
    if (tid < COUT) thr[tid] = thr_g[tid];
    __syncthreads();
    wmma::fragment<wmma::matrix_a, 16, 16, 8, wmma::precision::tf32, wmma::row_major> wfrag[16];
#pragma unroll
    for (int k = 0; k < 16; ++k)
        wmma::load_matrix_sync(wfrag[k], AC + (r * 16) * LDA + k * 8, LDA);
    __syncthreads();

    int done = 0;
    for (int ss = 0; ss < MAX_IT / TBATCH && !done; ++ss) {
        float ld = 0.f, lu = 0.f;

        for (int t = blockIdx.x; t < NTILES; t += G) {
            __syncthreads();
            if (tid < PT) {
                int p = t * PT + tid;
                int b = p / SP;
                int s = p - b * SP;
                cb[tid] = b * (COUT * SP) + s;
            }
            __syncthreads();
            // load u0 (always) and u (unless first super-step: u starts at 0)
            for (int idx = tid; idx < COUT * PT; idx += 512) {
                int c = idx >> 7;
                int j = idx & 127;
                int g = cb[j] + c * SP;
                U0[idx] = g_u0[g];
                U[idx]  = ss ? g_u[g] : 0.f;
            }
            __syncthreads();

#pragma unroll 1
            for (int s2 = 0; s2 < TBATCH; ++s2) {
                int k = ss * TBATCH + s2;
                // stage A = tf32(relu(u - thr)); k==0: a0 = relu(u0), no threshold
                if (k == 0) {
                    for (int idx = tid; idx < COUT * PT; idx += 512) {
                        float a = U0[idx];
                        a = a > 0.f ? a : 0.f;
                        AC[(idx >> 7) * LDA + (idx & 127)] = wmma::__float_to_tf32(a);
                    }
                } else {
                    for (int idx = tid; idx < COUT * PT; idx += 512) {
                        int c = idx >> 7;
                        float a = U[idx] - thr[c];
                        a = a > 0.f ? a : 0.f;
                        AC[c * LDA + (idx & 127)] = wmma::__float_to_tf32(a);
                    }
                }
                __syncthreads();
                // lateral GEMM: C[o][j] = sum_c Wr[o][c] * A[c][j]; Wr frags in registers
                wmma::fragment<wmma::accumulator, 16, 16, 8, float> acc[4];
#pragma unroll
                for (int q = 0; q < 4; ++q) wmma::fill_fragment(acc[q], 0.0f);
#pragma unroll
                for (int kk = 0; kk < 16; ++kk) {
#pragma unroll
                    for (int q = 0; q < 4; ++q) {
                        wmma::fragment<wmma::matrix_b, 16, 16, 8, wmma::precision::tf32, wmma::row_major> bf;
                        wmma::load_matrix_sync(bf, AC + (kk * 8) * LDA + (cg + q) * 16, LDA);
                        wmma::mma_sync(acc[q], wfrag[kk], bf, acc[q]);
                    }
                }
                __syncthreads();
#pragma unroll
                for (int q = 0; q < 4; ++q)
                    wmma::store_matrix_sync(AC + (r * 16) * LDA + (cg + q) * 16, acc[q], LDA, wmma::mem_row_major);
                __syncthreads();
                // elementwise update in smem; norms only on last sub-iteration
                for (int idx = tid; idx < COUT * PT; idx += 512) {
                    int o = idx >> 7;
                    int j = idx & 127;
                    float lat = AC[o * LDA + j];
                    float up  = (k == 0) ? 0.f : U[idx];
                    float un  = OMT * up + TAUF * (U0[idx] - lat);
                    U[idx] = un;
                    if (s2 == TBATCH - 1) {
                        float d = un - up;
                        ld += d * d;
                        lu += un * un;
                    }
                }
                __syncthreads();
            }
            // write u back
            for (int idx = tid; idx < COUT * PT; idx += 512) {
                int c = idx >> 7;
                int j = idx & 127;
                g_u[cb[j] + c * SP] = U[idx];
            }
        }

        // block reduction of norm partials
#pragma unroll
        for (int off = 16; off; off >>= 1) {
            ld += __shfl_down_sync(0xffffffffu, ld, off);
            lu += __shfl_down_sync(0xffffffffu, lu, off);
        }
        if (lane == 0) { red[warp] = ld; red[32 + warp] = lu; }
        __syncthreads();

        if (tid == 0) {
            float sd = 0.f, su = 0.f;
#pragma unroll
            for (int w2 = 0; w2 < 16; ++w2) { sd += red[w2]; su += red[32 + w2]; }
            atomicAdd((float*)&g_sd[ss & 1], sd);
            atomicAdd((float*)&g_su[ss & 1], su);
            __threadfence();
            unsigned old = atomicAdd(&g_bar, 1u);
            if (old == (unsigned)G - 1u) {
                float D = g_sd[ss & 1];
                float Un = g_su[ss & 1];
                int c2 = (sqrtf(D) < EPSF * sqrtf(Un)) ? 1 : 0;
                g_sd[(ss + 1) & 1] = 0.f;
                g_su[(ss + 1) & 1] = 0.f;
                g_conv = c2;
                atomicExch(&g_bar, 0u);
                __threadfence();
                g_go = ss + 1;
            } else {
                while (g_go < ss + 1) __nanosleep(100);
            }
            __threadfence();
            *flg = g_conv;
        }
        __syncthreads();
        done = *flg;
        __syncthreads();
    }

    // output: a_final = relu(u - thr)
    for (int t = blockIdx.x; t < NTILES; t += G) {
        __syncthreads();
        if (tid < PT) {
            int p = t * PT + tid;
            int b = p / SP;
            int s = p - b * SP;
            cb[tid] = b * (COUT * SP) + s;
        }
        __syncthreads();
        for (int idx = tid; idx < COUT * PT; idx += 512) {
            int o = idx >> 7;
            int j = idx & 127;
            float un = g_u[cb[j] + o * SP];
            float a = un - thr[o];
            out[cb[j] + o * SP] = a > 0.f ? a : 0.f;
        }
    }
}

// ---------------- launch ----------------
extern "C" void kernel_launch(void* const* d_in, const int* in_sizes, int n_in,
                              void* d_out, int out_size)
{
    const float* x    = (const float*)d_in[0];
    const float* Wff  = (const float*)d_in[1];
    const float* Wrec = (const float*)d_in[2];
    const float* thr  = (const float*)d_in[3];
    float* out = (float*)d_out;

    static int nsm = 0;
    static size_t smem_conv = 0, smem_iter = 0;
    if (nsm == 0) {
        cudaDeviceProp p;
        cudaGetDeviceProperties(&p, 0);
        nsm = p.multiProcessorCount;
        smem_conv = (size_t)(COUT * LDWC + CIN * LDA + COUT * LDA) * 4 + 2 * PT * 4;
        smem_iter = (size_t)(2 * COUT * PT + COUT * LDA + COUT) * 4
                    + PT * 4 + 64 * 4 + 16;
        cudaFuncSetAttribute(conv_kernel, cudaFuncAttributeMaxDynamicSharedMemorySize, (int)smem_conv);
        cudaFuncSetAttribute(iter_kernel, cudaFuncAttributeMaxDynamicSharedMemorySize, (int)smem_iter);
    }

    prep_kernel<<<64, 256>>>(Wff, Wrec);
    conv_kernel<<<NTILES, 512, smem_conv>>>(x);
    iter_kernel<<<nsm, 512, smem_iter>>>(thr, out);
}

// round 5
// speedup vs baseline: 3.8122x; 2.1654x over previous
#include <cuda_runtime.h>
#include <cuda_fp16.h>
#include <mma.h>

using namespace nvcuda;

// Problem constants
#define BATCH   64
#define CIN     64
#define COUT    128
#define HIN     64
#define HO      62
#define SP      3844            // 62*62 spatial per batch image
#define NPIX    246016          // BATCH * SP
#define PT      128             // pixels per tile
#define NTILES  1922            // NPIX / PT (exact)
#define MAX_IT  352
#define TBATCH  8               // iterations per tile visit between grid syncs
#define TAUF    0.2f
#define OMT     0.8f
#define EPSF    1.0e-4f

#define LDU0    132             // fp32 pad (conflict-free 8-row LDS)
#define LDAS    136             // fp16 pad (16B-aligned rows for ldmatrix)
#define LDWC    72              // conv weight smem pad (halfs)
#define LDXC    136             // conv x smem pad (halfs)
#define LDCC    132             // conv output smem pad (floats)

// ---------------- device scratch (static: no runtime allocation) ----------------
__device__ float  g_u0[BATCH * COUT * SP];   // 126 MB
__device__ float  g_u [BATCH * COUT * SP];   // 126 MB
__device__ __half g_Wth[9 * COUT * CIN];     // conv weights fp16, [shift][o][c]
__device__ __half g_Wrh[COUT * COUT];        // lateral weights fp16 = -W_rec, [o][c]
__device__ unsigned int g_bar;
__device__ volatile int g_go;
__device__ volatile int g_conv;
__device__ volatile float g_sd[2];
__device__ volatile float g_su[2];

// ---------------- prep: convert weights to fp16, reset control state ----------------
__global__ void prep_kernel(const float* __restrict__ Wff,
                            const float* __restrict__ Wrec)
{
    int i = blockIdx.x * blockDim.x + threadIdx.x;
    int stride = gridDim.x * blockDim.x;
    for (int idx = i; idx < 9 * COUT * CIN; idx += stride) {
        int s = idx / (COUT * CIN);
        int r = idx - s * (COUT * CIN);
        int o = r >> 6;
        int c = r & 63;
        g_Wth[idx] = __float2half_rn(Wff[(o * CIN + c) * 9 + s]);
    }
    for (int idx = i; idx < COUT * COUT; idx += stride) {
        g_Wrh[idx] = __float2half_rn(-Wrec[idx]);
    }
    if (i == 0) {
        g_bar = 0u;
        g_go = 0;
        g_conv = 0;
        g_sd[0] = 0.f; g_sd[1] = 0.f;
        g_su[0] = 0.f; g_su[1] = 0.f;
    }
}

// ---------------- conv: u0 = conv3x3(x, W_ff), VALID, via 9 shifted channel-GEMMs (fp16 wmma) ----------------
extern "C" __global__ void __launch_bounds__(512, 1)
conv_kernel(const float* __restrict__ x)
{
    extern __shared__ float smf[];
    __half* Ws = (__half*)smf;                    // [128][LDWC]
    __half* As = Ws + COUT * LDWC;                // [64][LDXC]
    float*  Cs = (float*)(As + CIN * LDXC);       // [128][LDCC]
    int*    xb = (int*)(Cs + COUT * LDCC);        // [128]
    int*    ob = xb + PT;                         // [128]

    int tid = threadIdx.x;
    int t = blockIdx.x;

    if (tid < PT) {
        int p = t * PT + tid;
        int b = p / SP;
        int s = p - b * SP;
        int h = s / HO;
        int w = s - h * HO;
        xb[tid] = (b * CIN) * (HIN * HIN) + h * HIN + w;
        ob[tid] = (b * COUT) * SP + s;
    }

    int warp = tid >> 5;
    int r  = warp >> 1;        // oc row-block 0..7
    int cg = (warp & 1) * 4;   // pixel col-block base (of 8)

    wmma::fragment<wmma::accumulator, 16, 16, 16, float> acc[4];
#pragma unroll
    for (int q = 0; q < 4; ++q) wmma::fill_fragment(acc[q], 0.0f);
    __syncthreads();

    for (int sft = 0; sft < 9; ++sft) {
        int kh = sft / 3;
        int kw = sft - 3 * kh;
        for (int idx = tid; idx < COUT * CIN; idx += 512) {
            int o = idx >> 6;
            int c = idx & 63;
            Ws[o * LDWC + c] = g_Wth[sft * (COUT * CIN) + idx];
        }
        for (int idx = tid; idx < CIN * PT; idx += 512) {
            int c = idx >> 7;
            int j = idx & 127;
            As[c * LDXC + j] = __float2half_rn(x[xb[j] + c * (HIN * HIN) + kh * HIN + kw]);
        }
        __syncthreads();
#pragma unroll
        for (int kt = 0; kt < 4; ++kt) {
            wmma::fragment<wmma::matrix_a, 16, 16, 16, __half, wmma::row_major> af;
            wmma::load_matrix_sync(af, Ws + (r * 16) * LDWC + kt * 16, LDWC);
#pragma unroll
            for (int q = 0; q < 4; ++q) {
                wmma::fragment<wmma::matrix_b, 16, 16, 16, __half, wmma::row_major> bf;
                wmma::load_matrix_sync(bf, As + (kt * 16) * LDXC + (cg + q) * 16, LDXC);
                wmma::mma_sync(acc[q], af, bf, acc[q]);
            }
        }
        __syncthreads();
    }
#pragma unroll
    for (int q = 0; q < 4; ++q)
        wmma::store_matrix_sync(Cs + (r * 16) * LDCC + (cg + q) * 16, acc[q], LDCC, wmma::mem_row_major);
    __syncthreads();

    for (int idx = tid; idx < COUT * PT; idx += 512) {
        int o = idx >> 7;
        int j = idx & 127;
        g_u0[ob[j] + o * SP] = Cs[o * LDCC + j];
    }
}

// ---------------- persistent iteration kernel (raw mma, u in accumulator regs) ----------------
// u_{k+1} = 0.8 u_k + 0.2 u0 + (-Wr) * (0.2 * relu(u_k - thr))
// 256 threads, 8 warps; each warp owns a 32(row=channel) x 64(col=pixel) C region.
// Accumulator tile is m16n8: column block nt spans 8 pixels -> j = jbase + 8*nt + c0 + (e&1).
extern "C" __global__ void __launch_bounds__(256, 1)
iter_kernel(const float* __restrict__ thr_g, float* __restrict__ out)
{
    extern __shared__ float smf[];
    float*  U0s  = smf;                           // [128][LDU0] f32
    float*  Uold = U0s + COUT * LDU0;             // [128][LDU0] f32 (norm stash)
    __half* As   = (__half*)(Uold + COUT * LDU0); // [128][LDAS] fp16 activations
    int*    cb   = (int*)(As + COUT * LDAS);      // [128]
    float*  red  = (float*)(cb + PT);             // [16]
    int*    flg  = (int*)(red + 16);

    const int tid  = threadIdx.x;
    const int warp = tid >> 5;
    const int lane = tid & 31;
    const int obase = (warp >> 1) * 32;   // 4 row groups
    const int jbase = (warp & 1) * 64;    // 2 col halves
    const int r0 = lane >> 2;
    const int c0 = (lane & 3) * 2;
    const int G  = gridDim.x;

    // thresholds for this thread's 4 row positions
    float thv[2][2];
#pragma unroll
    for (int mt = 0; mt < 2; ++mt)
#pragma unroll
        for (int h = 0; h < 2; ++h)
            thv[mt][h] = thr_g[obase + 16 * mt + r0 + 8 * h];

    // weight fragments (-Wr) from global fp16, row-major [o][c], permanently in regs
    unsigned wf[2][8][4];
#pragma unroll
    for (int mt = 0; mt < 2; ++mt) {
        int o1 = obase + 16 * mt + r0;
#pragma unroll
        for (int kt = 0; kt < 8; ++kt) {
            int c = kt * 16 + c0;
            wf[mt][kt][0] = *(const unsigned*)&g_Wrh[o1 * COUT + c];
            wf[mt][kt][1] = *(const unsigned*)&g_Wrh[(o1 + 8) * COUT + c];
            wf[mt][kt][2] = *(const unsigned*)&g_Wrh[o1 * COUT + c + 8];
            wf[mt][kt][3] = *(const unsigned*)&g_Wrh[(o1 + 8) * COUT + c + 8];
        }
    }

    // ldmatrix per-lane address components (x4: 2 row-halves x 2 col-halves)
    const int sel = lane >> 3;
    const int crow0 = (lane & 7) + 8 * (sel & 1);
    const int jls   = jbase + 8 * (sel >> 1);
    unsigned as_base = (unsigned)__cvta_generic_to_shared(As);

    float U[64];   // accumulator / resident u: [mt][nt][e] -> (mt*8+nt)*4+e

    int done = 0;
    for (int ss = 0; ss < MAX_IT / TBATCH && !done; ++ss) {
        float ld = 0.f, lu = 0.f;

        for (int t = blockIdx.x; t < NTILES; t += G) {
            __syncthreads();
            if (tid < PT) {
                int p = t * PT + tid;
                int b = p / SP;
                int s = p - b * SP;
                cb[tid] = b * (COUT * SP) + s;
            }
            __syncthreads();
            // stage u0 into smem (coalesced over pixels)
            for (int idx = tid; idx < COUT * PT; idx += 256) {
                int c = idx >> 7;
                int j = idx & 127;
                U0s[c * LDU0 + j] = g_u0[cb[j] + c * SP];
            }
            // load resident u into registers (scattered per mma layout)
            if (ss) {
#pragma unroll
                for (int mt = 0; mt < 2; ++mt)
#pragma unroll
                    for (int nt = 0; nt < 8; ++nt)
#pragma unroll
                        for (int e = 0; e < 4; ++e) {
                            int o = obase + 16 * mt + r0 + 8 * (e >> 1);
                            int j = jbase + 8 * nt + c0 + (e & 1);
                            U[(mt * 8 + nt) * 4 + e] = g_u[cb[j] + o * SP];
                        }
            }
            __syncthreads();

#pragma unroll 1
            for (int s2 = 0; s2 < TBATCH; ++s2) {
                const bool first = (ss == 0 && s2 == 0);
                const bool last  = (s2 == TBATCH - 1);
                // stage: As = fp16(0.2*relu(uold - thr));  U = 0.8*uold + 0.2*u0
#pragma unroll
                for (int mt = 0; mt < 2; ++mt)
#pragma unroll
                    for (int nt = 0; nt < 8; ++nt)
#pragma unroll
                        for (int h = 0; h < 2; ++h) {
                            int o = obase + 16 * mt + r0 + 8 * h;
                            int j = jbase + 8 * nt + c0;
                            int ui = (mt * 8 + nt) * 4 + h * 2;
                            float u00 = U0s[o * LDU0 + j];
                            float u01 = U0s[o * LDU0 + j + 1];
                            float uo0, uo1, th;
                            if (first) { uo0 = u00; uo1 = u01; th = 0.f; }
                            else       { uo0 = U[ui]; uo1 = U[ui + 1]; th = thv[mt][h]; }
                            float a0 = uo0 - th; a0 = a0 > 0.f ? a0 * TAUF : 0.f;
                            float a1 = uo1 - th; a1 = a1 > 0.f ? a1 * TAUF : 0.f;
                            *(__half2*)&As[o * LDAS + j] = __floats2half2_rn(a0, a1);
                            if (last) {
                                Uold[o * LDU0 + j]     = first ? 0.f : uo0;
                                Uold[o * LDU0 + j + 1] = first ? 0.f : uo1;
                            }
                            U[ui]     = first ? TAUF * u00 : OMT * uo0 + TAUF * u00;
                            U[ui + 1] = first ? TAUF * u01 : OMT * uo1 + TAUF * u01;
                        }
                __syncthreads();
                // GEMM: U += (-Wr) * a'   (mma.m16n8k16, B via ldmatrix.trans)
#pragma unroll
                for (int ntp = 0; ntp < 4; ++ntp) {
#pragma unroll
                    for (int kt = 0; kt < 8; ++kt) {
                        unsigned b0, b1, b2, b3;
                        unsigned addr = as_base +
                            (unsigned)(((crow0 + 16 * kt) * LDAS + jls + 16 * ntp) * 2);
                        asm volatile(
                            "ldmatrix.sync.aligned.m8n8.x4.trans.shared.b16 {%0,%1,%2,%3}, [%4];"
                            : "=r"(b0), "=r"(b1), "=r"(b2), "=r"(b3) : "r"(addr));
#pragma unroll
                        for (int mt = 0; mt < 2; ++mt) {
                            float* ca = &U[(mt * 8 + 2 * ntp) * 4];
                            asm volatile(
                                "mma.sync.aligned.m16n8k16.row.col.f32.f16.f16.f32 "
                                "{%0,%1,%2,%3}, {%4,%5,%6,%7}, {%8,%9}, {%0,%1,%2,%3};"
                                : "+f"(ca[0]), "+f"(ca[1]), "+f"(ca[2]), "+f"(ca[3])
                                : "r"(wf[mt][kt][0]), "r"(wf[mt][kt][1]),
                                  "r"(wf[mt][kt][2]), "r"(wf[mt][kt][3]),
                                  "r"(b0), "r"(b1));
                            float* cbr = &U[(mt * 8 + 2 * ntp + 1) * 4];
                            asm volatile(
                                "mma.sync.aligned.m16n8k16.row.col.f32.f16.f16.f32 "
                                "{%0,%1,%2,%3}, {%4,%5,%6,%7}, {%8,%9}, {%0,%1,%2,%3};"
                                : "+f"(cbr[0]), "+f"(cbr[1]), "+f"(cbr[2]), "+f"(cbr[3])
                                : "r"(wf[mt][kt][0]), "r"(wf[mt][kt][1]),
                                  "r"(wf[mt][kt][2]), "r"(wf[mt][kt][3]),
                                  "r"(b2), "r"(b3));
                        }
                    }
                }
                __syncthreads();
                if (last) {
#pragma unroll
                    for (int mt = 0; mt < 2; ++mt)
#pragma unroll
                        for (int nt = 0; nt < 8; ++nt)
#pragma unroll
                            for (int e = 0; e < 4; ++e) {
                                int o = obase + 16 * mt + r0 + 8 * (e >> 1);
                                int j = jbase + 8 * nt + c0 + (e & 1);
                                float un = U[(mt * 8 + nt) * 4 + e];
                                float d = un - Uold[o * LDU0 + j];
                                ld += d * d;
                                lu += un * un;
                            }
                }
            }
            // write u back
#pragma unroll
            for (int mt = 0; mt < 2; ++mt)
#pragma unroll
                for (int nt = 0; nt < 8; ++nt)
#pragma unroll
                    for (int e = 0; e < 4; ++e) {
                        int o = obase + 16 * mt + r0 + 8 * (e >> 1);
                        int j = jbase + 8 * nt + c0 + (e & 1);
                        g_u[cb[j] + o * SP] = U[(mt * 8 + nt) * 4 + e];
                    }
        }

        // block reduction of norm partials (8 warps)
#pragma unroll
        for (int off = 16; off; off >>= 1) {
            ld += __shfl_down_sync(0xffffffffu, ld, off);
            lu += __shfl_down_sync(0xffffffffu, lu, off);
        }
        if (lane == 0) { red[warp] = ld; red[8 + warp] = lu; }
        __syncthreads();

        if (tid == 0) {
            float sd = 0.f, su = 0.f;
#pragma unroll
            for (int w2 = 0; w2 < 8; ++w2) { sd += red[w2]; su += red[8 + w2]; }
            atomicAdd((float*)&g_sd[ss & 1], sd);
            atomicAdd((float*)&g_su[ss & 1], su);
            __threadfence();
            unsigned old = atomicAdd(&g_bar, 1u);
            if (old == (unsigned)G - 1u) {
                float D = g_sd[ss & 1];
                float Un = g_su[ss & 1];
                int c2 = (sqrtf(D) < EPSF * sqrtf(Un)) ? 1 : 0;
                g_sd[(ss + 1) & 1] = 0.f;
                g_su[(ss + 1) & 1] = 0.f;
                g_conv = c2;
                atomicExch(&g_bar, 0u);
                __threadfence();
                g_go = ss + 1;
            } else {
                while (g_go < ss + 1) __nanosleep(100);
            }
            __threadfence();
            *flg = g_conv;
        }
        __syncthreads();
        done = *flg;
        __syncthreads();
    }

    // output: a_final = relu(u - thr)
    for (int t = blockIdx.x; t < NTILES; t += G) {
        __syncthreads();
        if (tid < PT) {
            int p = t * PT + tid;
            int b = p / SP;
            int s = p - b * SP;
            cb[tid] = b * (COUT * SP) + s;
        }
        __syncthreads();
        for (int idx = tid; idx < COUT * PT; idx += 256) {
            int o = idx >> 7;
            int j = idx & 127;
            float un = g_u[cb[j] + o * SP];
            float a = un - __ldg(&thr_g[o]);
            out[cb[j] + o * SP] = a > 0.f ? a : 0.f;
        }
    }
}

// ---------------- launch ----------------
extern "C" void kernel_launch(void* const* d_in, const int* in_sizes, int n_in,
                              void* d_out, int out_size)
{
    const float* x    = (const float*)d_in[0];
    const float* Wff  = (const float*)d_in[1];
    const float* Wrec = (const float*)d_in[2];
    const float* thr  = (const float*)d_in[3];
    float* out = (float*)d_out;

    static int nsm = 0;
    static size_t smem_conv = 0, smem_iter = 0;
    if (nsm == 0) {
        cudaDeviceProp p;
        cudaGetDeviceProperties(&p, 0);
        nsm = p.multiProcessorCount;
        smem_conv = (size_t)(COUT * LDWC + CIN * LDXC) * 2
                  + (size_t)COUT * LDCC * 4 + 2 * PT * 4;
        smem_iter = (size_t)(2 * COUT * LDU0) * 4 + (size_t)COUT * LDAS * 2
                  + PT * 4 + 16 * 4 + 16;
        cudaFuncSetAttribute(conv_kernel, cudaFuncAttributeMaxDynamicSharedMemorySize, (int)smem_conv);
        cudaFuncSetAttribute(iter_kernel, cudaFuncAttributeMaxDynamicSharedMemorySize, (int)smem_iter);
    }

    prep_kernel<<<64, 256>>>(Wff, Wrec);
    conv_kernel<<<NTILES, 512, smem_conv>>>(x);
    iter_kernel<<<nsm, 256, smem_iter>>>(thr, out);
}